// round 13
// baseline (speedup 1.0000x reference)
#include <cuda_runtime.h>
#include <math.h>

// BinEmbedding: out[p] = emb_table[tok(x[p])]
//   tok = 0 if isnan(x), else clamp(count(bins <= x) - 1, 0) + 1
//
// out = 268 MB written; converged at the LTS/HBM write floor (~6.3 TB/s).
// R13: token flow via warp shuffle instead of smem round-trip.
//   Warp w searches exactly the 32 rows it later stores:
//     lane -> row = 2*w + (lane>>1)*16 + (lane&1)
//   Copy iter k: lanes 0-15 need row 2w+16k (held by lane 2k),
//                lanes 16-31 need row 2w+16k+1 (lane 2k+1)
//   -> tok = shfl(tok_mine, 2k + (lane>>4)); no stok smem, no 2nd barrier.

#define NUM_BINS 256
#define F4_PER_ROW 16                    // 64 floats / 4
#define THREADS 256
#define PPB 256                          // positions per block
#define COPY_ITERS 16
#define BATCH 8

__global__ __launch_bounds__(THREADS) void bin_embed_kernel(
    const float*  __restrict__ x,
    const float*  __restrict__ bins,
    const float4* __restrict__ emb4,     // (NUM_BINS+1) * 16 float4
    float4*       __restrict__ out)      // n_pos * 16 float4
{
    __shared__ float sbins[NUM_BINS];

    const int tid  = threadIdx.x;
    const int base = blockIdx.x * PPB;
    const int warp = tid >> 5;
    const int lane = tid & 31;

    sbins[tid] = bins[tid];              // THREADS == NUM_BINS
    __syncthreads();

    // ---- Phase 1: each warp searches the 32 rows it will store ----
    // lane -> row = 2*warp + (lane>>1)*16 + (lane&1)
    int my_tok;
    {
        int my_row = 2 * warp + ((lane >> 1) << 4) + (lane & 1);
        float v = __ldg(&x[base + my_row]);
        int c = 0;
        bool nn = isnan(v);
        #pragma unroll
        for (int s = NUM_BINS >> 1; s > 0; s >>= 1) {
            if (sbins[c + s - 1] <= v) c += s;
        }
        int i0 = c - 1; if (i0 < 0) i0 = 0;
        my_tok = nn ? 0 : i0 + 1;
    }
    // No barrier needed: tokens live in registers, exchanged via shuffle.

    // ---- Phase 2: gather + coalesced streaming stores, 8-wide batches ----
    // float4 element index = tid + k*THREADS; sub = tid & 15 invariant.
    // Token source lane for iter k: 2k + (lane>>4).
    const int sub  = tid & 15;
    const int half = lane >> 4;          // 0 for lanes 0-15, 1 for 16-31
    float4* outp   = out + (size_t)base * F4_PER_ROW + tid;

    #pragma unroll
    for (int b = 0; b < COPY_ITERS / BATCH; b++) {   // 2 batches
        int tok[BATCH];
        #pragma unroll
        for (int k = 0; k < BATCH; k++) {
            int kk = b * BATCH + k;
            tok[k] = __shfl_sync(0xFFFFFFFFu, my_tok, 2 * kk + half);
        }

        float4 val[BATCH];
        #pragma unroll
        for (int k = 0; k < BATCH; k++)
            val[k] = __ldg(&emb4[tok[k] * F4_PER_ROW + sub]);

        #pragma unroll
        for (int k = 0; k < BATCH; k++)
            __stcs(outp + (size_t)k * THREADS, val[k]);

        outp += (size_t)BATCH * THREADS;
    }
}

extern "C" void kernel_launch(void* const* d_in, const int* in_sizes, int n_in,
                              void* d_out, int out_size)
{
    const float*  x    = (const float*)d_in[0];
    const float*  bins = (const float*)d_in[1];
    const float4* emb4 = (const float4*)d_in[2];
    float4* out = (float4*)d_out;

    int n_pos  = in_sizes[0];            // 1,048,576; divisible by PPB
    int blocks = n_pos / PPB;            // 4096

    bin_embed_kernel<<<blocks, THREADS>>>(x, bins, emb4, out);
}

// round 14
// speedup vs baseline: 1.0111x; 1.0111x over previous
#include <cuda_runtime.h>
#include <math.h>

// BinEmbedding: out[p] = emb_table[tok(x[p])]
//   tok = 0 if isnan(x), else clamp(count(bins <= x) - 1, 0) + 1
//
// out = 268 MB written; at the LTS/HBM write floor (~6.3 TB/s wall).
// R14: ZERO block barriers. Warps fully decoupled:
//  - per-warp private bins copy in smem (8 x 1KB), loaded by each warp,
//    __syncwarp only
//  - R13 token flow: warp w searches exactly the 32 rows it stores,
//    lane -> row = 2*w + (lane>>1)*16 + (lane&1); copy iter k gets its
//    token via __shfl_sync(.., 2k + (lane>>4))
//  - copy phase: sub-invariant LDG.128 gathers, 8-wide batches, .cs stores

#define NUM_BINS 256
#define F4_PER_ROW 16                    // 64 floats / 4
#define THREADS 256
#define NWARPS (THREADS / 32)
#define PPB 256                          // positions per block
#define COPY_ITERS 16
#define BATCH 8

__global__ __launch_bounds__(THREADS) void bin_embed_kernel(
    const float*  __restrict__ x,
    const float*  __restrict__ bins,
    const float4* __restrict__ emb4,     // (NUM_BINS+1) * 16 float4
    float4*       __restrict__ out)      // n_pos * 16 float4
{
    __shared__ float sbins[NWARPS][NUM_BINS];   // per-warp private copies

    const int tid  = threadIdx.x;
    const int base = blockIdx.x * PPB;
    const int warp = tid >> 5;
    const int lane = tid & 31;

    // Each warp stages its own bins copy: 8 coalesced LDG per lane.
    float* wb = sbins[warp];
    #pragma unroll
    for (int i = 0; i < NUM_BINS / 32; i++)
        wb[lane + i * 32] = __ldg(&bins[lane + i * 32]);
    __syncwarp();

    // ---- Phase 1: each warp searches the 32 rows it will store ----
    // lane -> row = 2*warp + (lane>>1)*16 + (lane&1)
    int my_tok;
    {
        int my_row = 2 * warp + ((lane >> 1) << 4) + (lane & 1);
        float v = __ldg(&x[base + my_row]);
        int c = 0;
        bool nn = isnan(v);
        #pragma unroll
        for (int s = NUM_BINS >> 1; s > 0; s >>= 1) {
            if (wb[c + s - 1] <= v) c += s;
        }
        int i0 = c - 1; if (i0 < 0) i0 = 0;
        my_tok = nn ? 0 : i0 + 1;
    }
    // Tokens stay in registers; exchanged via shuffle. No block barrier.

    // ---- Phase 2: gather + coalesced streaming stores, 8-wide batches ----
    // float4 element index = tid + k*THREADS; sub = tid & 15 invariant.
    // Token source lane for iter k: 2k + (lane>>4).
    const int sub  = tid & 15;
    const int half = lane >> 4;          // 0 for lanes 0-15, 1 for 16-31
    float4* outp   = out + (size_t)base * F4_PER_ROW + tid;

    #pragma unroll
    for (int b = 0; b < COPY_ITERS / BATCH; b++) {   // 2 batches
        int tok[BATCH];
        #pragma unroll
        for (int k = 0; k < BATCH; k++) {
            int kk = b * BATCH + k;
            tok[k] = __shfl_sync(0xFFFFFFFFu, my_tok, 2 * kk + half);
        }

        float4 val[BATCH];
        #pragma unroll
        for (int k = 0; k < BATCH; k++)
            val[k] = __ldg(&emb4[tok[k] * F4_PER_ROW + sub]);

        #pragma unroll
        for (int k = 0; k < BATCH; k++)
            __stcs(outp + (size_t)k * THREADS, val[k]);

        outp += (size_t)BATCH * THREADS;
    }
}

extern "C" void kernel_launch(void* const* d_in, const int* in_sizes, int n_in,
                              void* d_out, int out_size)
{
    const float*  x    = (const float*)d_in[0];
    const float*  bins = (const float*)d_in[1];
    const float4* emb4 = (const float4*)d_in[2];
    float4* out = (float4*)d_out;

    int n_pos  = in_sizes[0];            // 1,048,576; divisible by PPB
    int blocks = n_pos / PPB;            // 4096

    bin_embed_kernel<<<blocks, THREADS>>>(x, bins, emb4, out);
}